// round 10
// baseline (speedup 1.0000x reference)
#include <cuda_runtime.h>

// Pruned RNNT loss — R10: 48 blocks (12 chunks x 4 batch-pairs), 576 threads.
// Each block builds TWO chunk operators (one per batch of its pair) via the
// 4-level product tree; halves the same-address ticket drain and block-finish
// spread vs 96 blocks. Winner combine = R9 meet-in-the-middle (forward vector
// x backward row on disjoint warps, one log-dot join). Single launch.

#define NEG    (-1.0e30f)
#define LOG2E  1.4426950408889634f
#define LN2f   0.6931471805599453f
#define LMAX   16
#define MAXB   8
#define MAXC   12
#define NROWS  (2*LMAX + 1)     // 33 raw diagonal rows per chunk window
#define HALF   288              // threads per batch-half of the block

__device__ float    g_ops[MAXB][MAXC][48];   // [b][chunk][row*8+col]
__device__ unsigned g_done = 0;

__device__ __forceinline__ float ex2f_(float x){float y;asm("ex2.approx.ftz.f32 %0,%1;":"=f"(y):"f"(x));return y;}
__device__ __forceinline__ float lg2f_(float x){float y;asm("lg2.approx.ftz.f32 %0,%1;":"=f"(y):"f"(x));return y;}

__device__ __forceinline__ unsigned ticket_acq_rel_(unsigned* p) {
    unsigned old;
    asm volatile("atom.acq_rel.gpu.add.u32 %0, [%1], 1;"
                 : "=r"(old) : "l"(p) : "memory");
    return old;
}

__device__ __forceinline__ float lse3_(float a, float b, float c) {
    float m = fmaxf(fmaxf(a, b), c);
    return m + lg2f_(ex2f_(a - m) + ex2f_(b - m) + ex2f_(c - m));
}
__device__ __forceinline__ float lse6_(float x0,float x1,float x2,float x3,float x4,float x5) {
    float m = fmaxf(fmaxf(fmaxf(x0,x1),fmaxf(x2,x3)),fmaxf(x4,x5));
    float s = ex2f_(x0-m)+ex2f_(x1-m)+ex2f_(x2-m)
            + ex2f_(x3-m)+ex2f_(x4-m)+ex2f_(x5-m);
    return m + lg2f_(s);
}
// dense 6x6 product entry: C[i][j] = LSE_k A[i][k] + B[k][j]  (row-major, pad 8)
__device__ __forceinline__ float lse6prod_(const float* A, const float* B, int i, int j) {
    return lse6_(A[i*8+0] + B[0*8+j], A[i*8+1] + B[1*8+j], A[i*8+2] + B[2*8+j],
                 A[i*8+3] + B[3*8+j], A[i*8+4] + B[4*8+j], A[i*8+5] + B[5*8+j]);
}

__global__ void __launch_bounds__(576) rnnt_kernel(
        const float* __restrict__ lp,   const int* __restrict__ tgt,
        const int*   __restrict__ tlen, const int* __restrict__ ulen,
        float* __restrict__ out, int T, int U, int V, int C, int B) {
    __shared__ float sEr[2][NROWS][8], sBr[2][NROWS][8];
    __shared__ float sG1[2][LMAX][8], sGm[2][LMAX][8], sG2[2][LMAX][8];
    __shared__ float sL1[2][8][48], sL2[2][4][48], sL3[2][2][48];
    __shared__ float s_ops[MAXB][MAXC][48];
    __shared__ float s_w[MAXB][8], s_y[MAXB][8];
    __shared__ int   s_len[MAXB][2];
    __shared__ float s_iv[MAXB][2];
    __shared__ int   s_last;

    const int chunk = blockIdx.x, bpair = blockIdx.y;
    const int tid = threadIdx.x, lane = tid & 31, w = tid >> 5;
    const int bl  = (tid >= HALF) ? 1 : 0;               // batch-local half
    const int ct  = tid - bl * HALF;                     // cell id within half
    const int bb  = 2 * bpair + bl;                      // global batch
    const int Ut  = U - 1;
    const int k0  = chunk * LMAX;
    const size_t sT = (size_t)U * V;
    const float* lpb  = lp + (size_t)bb * T * sT;
    const int*   tgtb = tgt + bb * Ut;

    // phase 0: lengths + init-vector scalars for ALL batches (overlaps gather)
    if (tid < B) {
        int b2 = tid;
        const float* lpb2 = lp + (size_t)b2 * T * sT;
        s_len[b2][0] = __ldg(tlen + b2);
        s_len[b2][1] = __ldg(ulen + b2);
        int tg0 = __ldg(tgt + b2 * Ut);
        s_iv[b2][0] = __ldg(lpb2) * LOG2E;               // gB(1,0)
        s_iv[b2][1] = __ldg(lpb2 + tg0) * LOG2E;         // gE(0,1)
    }

    // phase 1a: raw band gather, ONE cell per thread, static bound (198<288)
    if (ct < NROWS * 6) {
        int rr = ct / 6, s = ct - rr * 6;
        int d  = 2 * k0 + 1 + rr;
        int o  = 2 * s - 4 - (d & 1);
        int t  = (d - o) >> 1, u = (d + o) >> 1;
        bool ob = (o >= -5) && (o <= 5);
        float ev = NEG, bv = NEG;
        if (ob && t >= 0 && t < T && u >= 1 && u <= Ut)
            ev = __ldg(lpb + (size_t)t * sT + (size_t)(u - 1) * V + __ldg(tgtb + (u - 1)));
        if (ob && t >= 1 && t <= T && u >= 0 && u <= Ut)
            bv = __ldg(lpb + (size_t)(t - 1) * sT + (size_t)u * V);
        sEr[bl][rr][s] = ev; sBr[bl][rr][s] = bv;
    }
    __syncthreads();

    const int tl = s_len[bb][0], ul = s_len[bb][1];
    const int dmax = tl + ul, p = dmax & 1, K = dmax >> 1;

    // phase 1b: tridiagonal step operators (identity-pad beyond K) [96/half]
    if (ct < LMAX * 6) {
        int k = ct / 6, s = ct - k * 6;
        float G1, Gm, G2;
        if (k0 + k < K) {
            int rrd = 2 * k + p + 1, rrm = rrd - 1;
            int u   = k0 + k + s - 1;
            bool mU  = (u <= ul), mUl = (u - 1 <= ul);
            float Ed = mU ? sEr[bl][rrd][s] : NEG;
            float Bd = mU ? sBr[bl][rrd][s] : NEG;
            int sL = s - p, sR = s + 1 - p;
            float El = (sL >= 0 && mUl) ? sEr[bl][rrm][sL] : NEG;
            float Bl = (sL >= 0 && mUl) ? sBr[bl][rrm][sL] : NEG;
            float Er = (sR <= 5 && mU)  ? sEr[bl][rrm][sR] : NEG;
            float Br = (sR <= 5 && mU)  ? sBr[bl][rrm][sR] : NEG;
            G1 = (El + Ed) * LOG2E;                      // from slot s-1
            G2 = (Br + Bd) * LOG2E;                      // from slot s+1
            float a = (Bl + Ed) * LOG2E;
            float e = (Er + Bd) * LOG2E;
            float m = fmaxf(a, e);
            Gm = m + lg2f_(ex2f_(a - m) + ex2f_(e - m));
        } else { G1 = NEG; Gm = 0.0f; G2 = NEG; }        // identity
        sG1[bl][k][s] = G1; sGm[bl][k][s] = Gm; sG2[bl][k][s] = G2;
    }
    __syncthreads();

    // tree level 1: pairs of tridiag -> dense (penta) [288/half = 1 per thread]
    {
        int m = ct / 36, rem = ct - m * 36;
        int i = rem / 6, j = rem - i * 6;
        const int A = 2 * m + 1, Bt = 2 * m;             // B applied first
        float t0 = NEG, t1, t2 = NEG;
        int k;
        k = j - 1;
        if (k >= 0) {
            float a = (k == i-1) ? sG1[bl][A][i] : (k == i) ? sGm[bl][A][i] : (k == i+1) ? sG2[bl][A][i] : NEG;
            t0 = a + sG2[bl][Bt][k];
        }
        k = j;
        {
            float a = (k == i-1) ? sG1[bl][A][i] : (k == i) ? sGm[bl][A][i] : (k == i+1) ? sG2[bl][A][i] : NEG;
            t1 = a + sGm[bl][Bt][k];
        }
        k = j + 1;
        if (k <= 5) {
            float a = (k == i-1) ? sG1[bl][A][i] : (k == i) ? sGm[bl][A][i] : (k == i+1) ? sG2[bl][A][i] : NEG;
            t2 = a + sG1[bl][Bt][k];
        }
        sL1[bl][m][i*8 + j] = lse3_(t0, t1, t2);
    }
    __syncthreads();
    // level 2: 8 -> 4 [144/half]
    if (ct < 4 * 36) {
        int m = ct / 36, rem = ct - m * 36;
        int i = rem / 6, j = rem - i * 6;
        sL2[bl][m][i*8 + j] = lse6prod_(sL1[bl][2*m + 1], sL1[bl][2*m], i, j);
    }
    __syncthreads();
    // level 3: 4 -> 2 [72/half]
    if (ct < 2 * 36) {
        int m = ct / 36, rem = ct - m * 36;
        int i = rem / 6, j = rem - i * 6;
        sL3[bl][m][i*8 + j] = lse6prod_(sL2[bl][2*m + 1], sL2[bl][2*m], i, j);
    }
    __syncthreads();
    // level 4: 2 -> 1 [36/half], write the chunk operator to global
    if (ct < 36) {
        int i = ct / 6, j = ct - i * 6;
        g_ops[bb][chunk][i*8 + j] = lse6prod_(sL3[bl][1], sL3[bl][0], i, j);
    }
    // fence-free ticket: bar.sync (CTA link) + acq_rel atomic (gpu link)
    __syncthreads();
    if (tid == 0) {
        unsigned tk = ticket_acq_rel_(&g_done);
        s_last = (tk == (unsigned)(C * B / 2 - 1)) ? 1 : 0;
    }
    __syncthreads();
    if (!s_last) return;

    // winner: stage all operators into smem — compile-time-unrolled copy (MLP)
    {
        const float4* src = (const float4*)&g_ops[0][0][0];
        float4*       dst = (float4*)&s_ops[0][0][0];
        const int n4 = MAXB * MAXC * 48 / 4;             // 1152
        #pragma unroll
        for (int r = 0; r < (n4 + 575) / 576; ++r) {
            int i = tid + r * 576;
            if (i < n4) dst[i] = __ldcg(src + i);
        }
    }
    __syncthreads();

    const int F = (C + 1) >> 1;                          // forward op count (6)

    // winner: FORWARD half — warps 0-1, 4 batches/warp (width-8 groups)
    if (w < 2) {
        const int g  = lane >> 3, sl = lane & 7;
        const int bw = w * 4 + g;
        const int s  = min(sl, 5);
        const int tlw = s_len[bw][0], ulw = s_len[bw][1];
        const int pw  = (tlw + ulw) & 1;
        float v;
        if (pw == 0) v = (sl == 2) ? 0.0f : NEG;
        else         v = (sl == 2) ? s_iv[bw][0] : ((sl == 3) ? s_iv[bw][1] : NEG);

        const float* opp = &s_ops[bw][0][s*8];           // row s of op 0
        float o0=opp[0],o1=opp[1],o2=opp[2],o3=opp[3],o4=opp[4],o5=opp[5];
        for (int cc = 0; cc < F; ++cc) {
            const float* npp = &s_ops[bw][min(cc + 1, F - 1)][s*8];
            float q0=npp[0],q1=npp[1],q2=npp[2],q3=npp[3],q4=npp[4],q5=npp[5];
            float v0 = __shfl_sync(0xffffffffu, v, 0, 8);
            float v1 = __shfl_sync(0xffffffffu, v, 1, 8);
            float v2 = __shfl_sync(0xffffffffu, v, 2, 8);
            float v3 = __shfl_sync(0xffffffffu, v, 3, 8);
            float v4 = __shfl_sync(0xffffffffu, v, 4, 8);
            float v5 = __shfl_sync(0xffffffffu, v, 5, 8);
            v = lse6_(o0 + v0, o1 + v1, o2 + v2, o3 + v3, o4 + v4, o5 + v5);
            o0=q0;o1=q1;o2=q2;o3=q3;o4=q4;o5=q5;
        }
        s_w[bw][sl] = v;
    }

    // winner: BACKWARD half — warps 2-3, 4 batches/warp (width-8 groups)
    if (w >= 2 && w < 4) {
        const int g  = lane >> 3, sl = lane & 7;
        const int bw = (w - 2) * 4 + g;
        const int s  = min(sl, 5);
        const int tlw = s_len[bw][0], ulw = s_len[bw][1];
        const int pw  = (tlw + ulw) & 1;
        const int slot_star = (ulw - tlw + 4 + pw) >> 1;
        float y = (sl == slot_star) ? 0.0f : NEG;

        const float* opp = &s_ops[bw][C-1][0];           // column s of op C-1
        float o0=opp[0*8+s],o1=opp[1*8+s],o2=opp[2*8+s],
              o3=opp[3*8+s],o4=opp[4*8+s],o5=opp[5*8+s];
        for (int cc = C - 1; cc >= F; --cc) {
            const float* npp = &s_ops[bw][max(cc - 1, F)][0];
            float q0=npp[0*8+s],q1=npp[1*8+s],q2=npp[2*8+s],
                  q3=npp[3*8+s],q4=npp[4*8+s],q5=npp[5*8+s];
            float y0 = __shfl_sync(0xffffffffu, y, 0, 8);
            float y1 = __shfl_sync(0xffffffffu, y, 1, 8);
            float y2 = __shfl_sync(0xffffffffu, y, 2, 8);
            float y3 = __shfl_sync(0xffffffffu, y, 3, 8);
            float y4 = __shfl_sync(0xffffffffu, y, 4, 8);
            float y5 = __shfl_sync(0xffffffffu, y, 5, 8);
            y = lse6_(y0 + o0, y1 + o1, y2 + o2, y3 + o3, y4 + o4, y5 + o5);
            o0=q0;o1=q1;o2=q2;o3=q3;o4=q4;o5=q5;
        }
        s_y[bw][sl] = y;
    }
    __syncthreads();

    // winner: join — warp 0 lanes 0..7, one batch per lane: LSE_k(w_k + y_k)
    if (w == 0) {
        float r = 0.0f;
        if (lane < B) {
            const float* wv = &s_w[lane][0];
            const float* yv = &s_y[lane][0];
            float dot = lse6_(wv[0] + yv[0], wv[1] + yv[1], wv[2] + yv[2],
                              wv[3] + yv[3], wv[4] + yv[4], wv[5] + yv[5]);
            r = -dot * LN2f;
        }
        #pragma unroll
        for (int wd = 4; wd; wd >>= 1) r += __shfl_xor_sync(0xffffffffu, r, wd, 8);
        if (lane == 0) { out[0] = r * (1.0f / (float)B); g_done = 0; }
    }
}

extern "C" void kernel_launch(void* const* d_in, const int* in_sizes, int n_in,
                              void* d_out, int out_size) {
    const float* lp   = (const float*)d_in[0];   // [B,T,U,V] fp32
    const int*   tgt  = (const int*)  d_in[1];   // [B,U-1]
    const int*   tlen = (const int*)  d_in[2];   // [B]
    const int*   ulen = (const int*)  d_in[3];   // [B]

    const int B  = in_sizes[2];
    const int Ut = in_sizes[1] / B;
    const int U  = Ut + 1;
    const int V  = 512;
    const int T  = (int)(in_sizes[0] / ((long long)B * U * V));

    const int Kg = (T + U - 1) >> 1;             // max composed k-steps (192)
    int C = (Kg + LMAX - 1) / LMAX;              // chunks (dataset: 12)
    if (C < 1) C = 1;
    if (C > MAXC) C = MAXC;

    dim3 grid(C, B / 2);                         // 12 x 4 = 48 blocks
    rnnt_kernel<<<grid, 576>>>(lp, tgt, tlen, ulen, (float*)d_out, T, U, V, C, B);
}

// round 11
// speedup vs baseline: 1.2704x; 1.2704x over previous
#include <cuda_runtime.h>

// Pruned RNNT loss — R10: 48 blocks (12 chunks x 4 batch-pairs), 576 threads.
// Each block builds TWO chunk operators (one per batch of its pair) via the
// 4-level product tree; halves the same-address ticket drain and block-finish
// spread vs 96 blocks. Winner combine = R9 meet-in-the-middle (forward vector
// x backward row on disjoint warps, one log-dot join). Single launch.

#define NEG    (-1.0e30f)
#define LOG2E  1.4426950408889634f
#define LN2f   0.6931471805599453f
#define LMAX   16
#define MAXB   8
#define MAXC   12
#define NROWS  (2*LMAX + 1)     // 33 raw diagonal rows per chunk window
#define HALF   288              // threads per batch-half of the block

__device__ float    g_ops[MAXB][MAXC][48];   // [b][chunk][row*8+col]
__device__ unsigned g_done = 0;

__device__ __forceinline__ float ex2f_(float x){float y;asm("ex2.approx.ftz.f32 %0,%1;":"=f"(y):"f"(x));return y;}
__device__ __forceinline__ float lg2f_(float x){float y;asm("lg2.approx.ftz.f32 %0,%1;":"=f"(y):"f"(x));return y;}

__device__ __forceinline__ unsigned ticket_acq_rel_(unsigned* p) {
    unsigned old;
    asm volatile("atom.acq_rel.gpu.add.u32 %0, [%1], 1;"
                 : "=r"(old) : "l"(p) : "memory");
    return old;
}

__device__ __forceinline__ float lse3_(float a, float b, float c) {
    float m = fmaxf(fmaxf(a, b), c);
    return m + lg2f_(ex2f_(a - m) + ex2f_(b - m) + ex2f_(c - m));
}
__device__ __forceinline__ float lse6_(float x0,float x1,float x2,float x3,float x4,float x5) {
    float m = fmaxf(fmaxf(fmaxf(x0,x1),fmaxf(x2,x3)),fmaxf(x4,x5));
    float s = ex2f_(x0-m)+ex2f_(x1-m)+ex2f_(x2-m)
            + ex2f_(x3-m)+ex2f_(x4-m)+ex2f_(x5-m);
    return m + lg2f_(s);
}
// dense 6x6 product entry: C[i][j] = LSE_k A[i][k] + B[k][j]  (row-major, pad 8)
__device__ __forceinline__ float lse6prod_(const float* A, const float* B, int i, int j) {
    return lse6_(A[i*8+0] + B[0*8+j], A[i*8+1] + B[1*8+j], A[i*8+2] + B[2*8+j],
                 A[i*8+3] + B[3*8+j], A[i*8+4] + B[4*8+j], A[i*8+5] + B[5*8+j]);
}

__global__ void __launch_bounds__(576) rnnt_kernel(
        const float* __restrict__ lp,   const int* __restrict__ tgt,
        const int*   __restrict__ tlen, const int* __restrict__ ulen,
        float* __restrict__ out, int T, int U, int V, int C, int B) {
    __shared__ float sEr[2][NROWS][8], sBr[2][NROWS][8];
    __shared__ float sG1[2][LMAX][8], sGm[2][LMAX][8], sG2[2][LMAX][8];
    __shared__ float sL1[2][8][48], sL2[2][4][48], sL3[2][2][48];
    __shared__ float s_ops[MAXB][MAXC][48];
    __shared__ float s_w[MAXB][8], s_y[MAXB][8];
    __shared__ int   s_len[MAXB][2];
    __shared__ float s_iv[MAXB][2];
    __shared__ int   s_last;

    const int chunk = blockIdx.x, bpair = blockIdx.y;
    const int tid = threadIdx.x, lane = tid & 31, w = tid >> 5;
    const int bl  = (tid >= HALF) ? 1 : 0;               // batch-local half
    const int ct  = tid - bl * HALF;                     // cell id within half
    const int bb  = 2 * bpair + bl;                      // global batch
    const int Ut  = U - 1;
    const int k0  = chunk * LMAX;
    const size_t sT = (size_t)U * V;
    const float* lpb  = lp + (size_t)bb * T * sT;
    const int*   tgtb = tgt + bb * Ut;

    // phase 0: lengths + init-vector scalars for ALL batches (overlaps gather)
    if (tid < B) {
        int b2 = tid;
        const float* lpb2 = lp + (size_t)b2 * T * sT;
        s_len[b2][0] = __ldg(tlen + b2);
        s_len[b2][1] = __ldg(ulen + b2);
        int tg0 = __ldg(tgt + b2 * Ut);
        s_iv[b2][0] = __ldg(lpb2) * LOG2E;               // gB(1,0)
        s_iv[b2][1] = __ldg(lpb2 + tg0) * LOG2E;         // gE(0,1)
    }

    // phase 1a: raw band gather, ONE cell per thread, static bound (198<288)
    if (ct < NROWS * 6) {
        int rr = ct / 6, s = ct - rr * 6;
        int d  = 2 * k0 + 1 + rr;
        int o  = 2 * s - 4 - (d & 1);
        int t  = (d - o) >> 1, u = (d + o) >> 1;
        bool ob = (o >= -5) && (o <= 5);
        float ev = NEG, bv = NEG;
        if (ob && t >= 0 && t < T && u >= 1 && u <= Ut)
            ev = __ldg(lpb + (size_t)t * sT + (size_t)(u - 1) * V + __ldg(tgtb + (u - 1)));
        if (ob && t >= 1 && t <= T && u >= 0 && u <= Ut)
            bv = __ldg(lpb + (size_t)(t - 1) * sT + (size_t)u * V);
        sEr[bl][rr][s] = ev; sBr[bl][rr][s] = bv;
    }
    __syncthreads();

    const int tl = s_len[bb][0], ul = s_len[bb][1];
    const int dmax = tl + ul, p = dmax & 1, K = dmax >> 1;

    // phase 1b: tridiagonal step operators (identity-pad beyond K) [96/half]
    if (ct < LMAX * 6) {
        int k = ct / 6, s = ct - k * 6;
        float G1, Gm, G2;
        if (k0 + k < K) {
            int rrd = 2 * k + p + 1, rrm = rrd - 1;
            int u   = k0 + k + s - 1;
            bool mU  = (u <= ul), mUl = (u - 1 <= ul);
            float Ed = mU ? sEr[bl][rrd][s] : NEG;
            float Bd = mU ? sBr[bl][rrd][s] : NEG;
            int sL = s - p, sR = s + 1 - p;
            float El = (sL >= 0 && mUl) ? sEr[bl][rrm][sL] : NEG;
            float Bl = (sL >= 0 && mUl) ? sBr[bl][rrm][sL] : NEG;
            float Er = (sR <= 5 && mU)  ? sEr[bl][rrm][sR] : NEG;
            float Br = (sR <= 5 && mU)  ? sBr[bl][rrm][sR] : NEG;
            G1 = (El + Ed) * LOG2E;                      // from slot s-1
            G2 = (Br + Bd) * LOG2E;                      // from slot s+1
            float a = (Bl + Ed) * LOG2E;
            float e = (Er + Bd) * LOG2E;
            float m = fmaxf(a, e);
            Gm = m + lg2f_(ex2f_(a - m) + ex2f_(e - m));
        } else { G1 = NEG; Gm = 0.0f; G2 = NEG; }        // identity
        sG1[bl][k][s] = G1; sGm[bl][k][s] = Gm; sG2[bl][k][s] = G2;
    }
    __syncthreads();

    // tree level 1: pairs of tridiag -> dense (penta) [288/half = 1 per thread]
    {
        int m = ct / 36, rem = ct - m * 36;
        int i = rem / 6, j = rem - i * 6;
        const int A = 2 * m + 1, Bt = 2 * m;             // B applied first
        float t0 = NEG, t1, t2 = NEG;
        int k;
        k = j - 1;
        if (k >= 0) {
            float a = (k == i-1) ? sG1[bl][A][i] : (k == i) ? sGm[bl][A][i] : (k == i+1) ? sG2[bl][A][i] : NEG;
            t0 = a + sG2[bl][Bt][k];
        }
        k = j;
        {
            float a = (k == i-1) ? sG1[bl][A][i] : (k == i) ? sGm[bl][A][i] : (k == i+1) ? sG2[bl][A][i] : NEG;
            t1 = a + sGm[bl][Bt][k];
        }
        k = j + 1;
        if (k <= 5) {
            float a = (k == i-1) ? sG1[bl][A][i] : (k == i) ? sGm[bl][A][i] : (k == i+1) ? sG2[bl][A][i] : NEG;
            t2 = a + sG1[bl][Bt][k];
        }
        sL1[bl][m][i*8 + j] = lse3_(t0, t1, t2);
    }
    __syncthreads();
    // level 2: 8 -> 4 [144/half]
    if (ct < 4 * 36) {
        int m = ct / 36, rem = ct - m * 36;
        int i = rem / 6, j = rem - i * 6;
        sL2[bl][m][i*8 + j] = lse6prod_(sL1[bl][2*m + 1], sL1[bl][2*m], i, j);
    }
    __syncthreads();
    // level 3: 4 -> 2 [72/half]
    if (ct < 2 * 36) {
        int m = ct / 36, rem = ct - m * 36;
        int i = rem / 6, j = rem - i * 6;
        sL3[bl][m][i*8 + j] = lse6prod_(sL2[bl][2*m + 1], sL2[bl][2*m], i, j);
    }
    __syncthreads();
    // level 4: 2 -> 1 [36/half], write the chunk operator to global
    if (ct < 36) {
        int i = ct / 6, j = ct - i * 6;
        g_ops[bb][chunk][i*8 + j] = lse6prod_(sL3[bl][1], sL3[bl][0], i, j);
    }
    // fence-free ticket: bar.sync (CTA link) + acq_rel atomic (gpu link)
    __syncthreads();
    if (tid == 0) {
        unsigned tk = ticket_acq_rel_(&g_done);
        s_last = (tk == (unsigned)(C * B / 2 - 1)) ? 1 : 0;
    }
    __syncthreads();
    if (!s_last) return;

    // winner: stage all operators into smem — compile-time-unrolled copy (MLP)
    {
        const float4* src = (const float4*)&g_ops[0][0][0];
        float4*       dst = (float4*)&s_ops[0][0][0];
        const int n4 = MAXB * MAXC * 48 / 4;             // 1152
        #pragma unroll
        for (int r = 0; r < (n4 + 575) / 576; ++r) {
            int i = tid + r * 576;
            if (i < n4) dst[i] = __ldcg(src + i);
        }
    }
    __syncthreads();

    const int F = (C + 1) >> 1;                          // forward op count (6)

    // winner: FORWARD half — warps 0-1, 4 batches/warp (width-8 groups)
    if (w < 2) {
        const int g  = lane >> 3, sl = lane & 7;
        const int bw = w * 4 + g;
        const int s  = min(sl, 5);
        const int tlw = s_len[bw][0], ulw = s_len[bw][1];
        const int pw  = (tlw + ulw) & 1;
        float v;
        if (pw == 0) v = (sl == 2) ? 0.0f : NEG;
        else         v = (sl == 2) ? s_iv[bw][0] : ((sl == 3) ? s_iv[bw][1] : NEG);

        const float* opp = &s_ops[bw][0][s*8];           // row s of op 0
        float o0=opp[0],o1=opp[1],o2=opp[2],o3=opp[3],o4=opp[4],o5=opp[5];
        for (int cc = 0; cc < F; ++cc) {
            const float* npp = &s_ops[bw][min(cc + 1, F - 1)][s*8];
            float q0=npp[0],q1=npp[1],q2=npp[2],q3=npp[3],q4=npp[4],q5=npp[5];
            float v0 = __shfl_sync(0xffffffffu, v, 0, 8);
            float v1 = __shfl_sync(0xffffffffu, v, 1, 8);
            float v2 = __shfl_sync(0xffffffffu, v, 2, 8);
            float v3 = __shfl_sync(0xffffffffu, v, 3, 8);
            float v4 = __shfl_sync(0xffffffffu, v, 4, 8);
            float v5 = __shfl_sync(0xffffffffu, v, 5, 8);
            v = lse6_(o0 + v0, o1 + v1, o2 + v2, o3 + v3, o4 + v4, o5 + v5);
            o0=q0;o1=q1;o2=q2;o3=q3;o4=q4;o5=q5;
        }
        s_w[bw][sl] = v;
    }

    // winner: BACKWARD half — warps 2-3, 4 batches/warp (width-8 groups)
    if (w >= 2 && w < 4) {
        const int g  = lane >> 3, sl = lane & 7;
        const int bw = (w - 2) * 4 + g;
        const int s  = min(sl, 5);
        const int tlw = s_len[bw][0], ulw = s_len[bw][1];
        const int pw  = (tlw + ulw) & 1;
        const int slot_star = (ulw - tlw + 4 + pw) >> 1;
        float y = (sl == slot_star) ? 0.0f : NEG;

        const float* opp = &s_ops[bw][C-1][0];           // column s of op C-1
        float o0=opp[0*8+s],o1=opp[1*8+s],o2=opp[2*8+s],
              o3=opp[3*8+s],o4=opp[4*8+s],o5=opp[5*8+s];
        for (int cc = C - 1; cc >= F; --cc) {
            const float* npp = &s_ops[bw][max(cc - 1, F)][0];
            float q0=npp[0*8+s],q1=npp[1*8+s],q2=npp[2*8+s],
                  q3=npp[3*8+s],q4=npp[4*8+s],q5=npp[5*8+s];
            float y0 = __shfl_sync(0xffffffffu, y, 0, 8);
            float y1 = __shfl_sync(0xffffffffu, y, 1, 8);
            float y2 = __shfl_sync(0xffffffffu, y, 2, 8);
            float y3 = __shfl_sync(0xffffffffu, y, 3, 8);
            float y4 = __shfl_sync(0xffffffffu, y, 4, 8);
            float y5 = __shfl_sync(0xffffffffu, y, 5, 8);
            y = lse6_(y0 + o0, y1 + o1, y2 + o2, y3 + o3, y4 + o4, y5 + o5);
            o0=q0;o1=q1;o2=q2;o3=q3;o4=q4;o5=q5;
        }
        s_y[bw][sl] = y;
    }
    __syncthreads();

    // winner: join — warp 0 lanes 0..7, one batch per lane: LSE_k(w_k + y_k)
    if (w == 0) {
        float r = 0.0f;
        if (lane < B) {
            const float* wv = &s_w[lane][0];
            const float* yv = &s_y[lane][0];
            float dot = lse6_(wv[0] + yv[0], wv[1] + yv[1], wv[2] + yv[2],
                              wv[3] + yv[3], wv[4] + yv[4], wv[5] + yv[5]);
            r = -dot * LN2f;
        }
        #pragma unroll
        for (int wd = 4; wd; wd >>= 1) r += __shfl_xor_sync(0xffffffffu, r, wd, 8);
        if (lane == 0) { out[0] = r * (1.0f / (float)B); g_done = 0; }
    }
}

extern "C" void kernel_launch(void* const* d_in, const int* in_sizes, int n_in,
                              void* d_out, int out_size) {
    const float* lp   = (const float*)d_in[0];   // [B,T,U,V] fp32
    const int*   tgt  = (const int*)  d_in[1];   // [B,U-1]
    const int*   tlen = (const int*)  d_in[2];   // [B]
    const int*   ulen = (const int*)  d_in[3];   // [B]

    const int B  = in_sizes[2];
    const int Ut = in_sizes[1] / B;
    const int U  = Ut + 1;
    const int V  = 512;
    const int T  = (int)(in_sizes[0] / ((long long)B * U * V));

    const int Kg = (T + U - 1) >> 1;             // max composed k-steps (192)
    int C = (Kg + LMAX - 1) / LMAX;              // chunks (dataset: 12)
    if (C < 1) C = 1;
    if (C > MAXC) C = MAXC;

    dim3 grid(C, B / 2);                         // 12 x 4 = 48 blocks
    rnnt_kernel<<<grid, 576>>>(lp, tgt, tlen, ulen, (float*)d_out, T, U, V, C, B);
}